// round 1
// baseline (speedup 1.0000x reference)
#include <cuda_runtime.h>
#include <cuda_bf16.h>
#include <utility>
#include <cstddef>

// ---------------------------------------------------------------------------
// Compile-time reproduction of the reference codebook.
//
// reference: np.random.RandomState(0).choice([1.0f,3.0f], size=(512,8))
// Legacy RandomState.randint(0, 2, dtype=int64) path:
//   random_bounded_uint64_fill -> rng=1 <= 0xFFFFFFFF -> masked 32-bit draws:
//   idx[k] = mt19937_next32_tempered() & 1   (no rejection since mask==rng==1)
// Grid row r, element j uses draw k = r*8 + j; value = 1 + 2*idx.
// Only the PATTERN (8-bit mask of which elements are 3) matters for the
// output: duplicates in the 512-entry table dequantize identically.
// ---------------------------------------------------------------------------

struct Tables { bool present[256]; };

__host__ __device__ constexpr unsigned mt_temper(unsigned y) {
    y ^= (y >> 11);
    y ^= (y << 7)  & 0x9d2c5680u;
    y ^= (y << 15) & 0xefc60000u;
    y ^= (y >> 18);
    return y;
}

__host__ __device__ constexpr Tables make_tables() {
    unsigned mt[624] = {};
    {
        unsigned s = 0u;  // seed = 0
        for (int i = 0; i < 624; ++i) {
            mt[i] = s;
            s = 1812433253u * (s ^ (s >> 30)) + (unsigned)(i + 1);
        }
    }
    int pos = 624;
    Tables t{};
    for (int i = 0; i < 256; ++i) t.present[i] = false;
    for (int r = 0; r < 512; ++r) {
        unsigned p = 0;
        for (int j = 0; j < 8; ++j) {
            if (pos == 624) {
                for (int i = 0; i < 624; ++i) {
                    unsigned y = (mt[i] & 0x80000000u) | (mt[(i + 1) % 624] & 0x7fffffffu);
                    mt[i] = mt[(i + 397) % 624] ^ (y >> 1) ^ ((y & 1u) ? 0x9908b0dfu : 0u);
                }
                pos = 0;
            }
            unsigned bit = mt_temper(mt[pos++]) & 1u;
            p |= bit << j;
        }
        t.present[p] = true;
    }
    return t;
}

constexpr Tables TBL = make_tables();

__host__ __device__ constexpr int popc8(int p) {
    int k = 0;
    for (int j = 0; j < 8; ++j) k += (p >> j) & 1;
    return k;
}

// ---------------------------------------------------------------------------
// Per-thread state (all arrays compile-time indexed -> stays in registers)
// ---------------------------------------------------------------------------
struct St {
    float ulo[16];   // ulo[l] = S + 2*T_lo(l)   (fused, single rounding)
    float th2[16];   // th2[h] = 2*T_hi(h)       (exact: *2)
    float gmax[9];   // per-popcount-group max of u = dot(a, q)
    int   gidx[9];   // pattern achieving the group max
};

template <int P>
__device__ __forceinline__ void step(St& s) {
    if constexpr (TBL.present[P]) {
        constexpr int K = popc8(P);
        constexpr int L = P & 15;
        constexpr int H = P >> 4;
        float u;
        if constexpr (H == 0) u = s.ulo[L];
        else                  u = s.ulo[L] + s.th2[H];
        if (u > s.gmax[K]) { s.gmax[K] = u; s.gidx[K] = P; }
    }
}

template <size_t... Ps>
__device__ __forceinline__ void run_all(St& s, std::index_sequence<Ps...>) {
    (step<(int)Ps>(s), ...);
}

// ---------------------------------------------------------------------------
// Main kernel: one thread per 8-element block.
// ---------------------------------------------------------------------------
__global__ void __launch_bounds__(256)
iq2xs_kernel(const float* __restrict__ w, float* __restrict__ out, int nb) {
    int b = blockIdx.x * 256 + threadIdx.x;
    if (b >= nb) return;

    const float4* w4 = reinterpret_cast<const float4*>(w) + 2 * (size_t)b;
    float4 v0 = w4[0];
    float4 v1 = w4[1];
    float wv[8] = {v0.x, v0.y, v0.z, v0.w, v1.x, v1.y, v1.z, v1.w};

    float a[8];
#pragma unroll
    for (int i = 0; i < 8; ++i) a[i] = fabsf(wv[i]);

    // Subset-sum DP over low half (elements 0..3) and high half (4..7).
    float tlo[16], thi[16];
    tlo[0] = 0.f;
    tlo[1] = a[0];
    tlo[2] = a[1];
    tlo[3] = tlo[1] + a[1];
    tlo[4] = a[2];
    tlo[5] = tlo[1] + a[2];
    tlo[6] = tlo[2] + a[2];
    tlo[7] = tlo[3] + a[2];
#pragma unroll
    for (int m = 0; m < 8; ++m) tlo[8 + m] = tlo[m] + a[3];

    thi[0] = 0.f;
    thi[1] = a[4];
    thi[2] = a[5];
    thi[3] = thi[1] + a[5];
    thi[4] = a[6];
    thi[5] = thi[1] + a[6];
    thi[6] = thi[2] + a[6];
    thi[7] = thi[3] + a[6];
#pragma unroll
    for (int m = 0; m < 8; ++m) thi[8 + m] = thi[m] + a[7];

    float S = tlo[15] + thi[15];   // sum of all |w| in block

    St s;
#pragma unroll
    for (int l = 0; l < 16; ++l) s.ulo[l] = fmaf(2.f, tlo[l], S);
#pragma unroll
    for (int h = 0; h < 16; ++h) s.th2[h] = 2.f * thi[h];
#pragma unroll
    for (int k = 0; k < 9; ++k) { s.gmax[k] = -1.f; s.gidx[k] = 0; }

    // Fully unrolled scan over present patterns, grouped by popcount so the
    // norm divide stays out of the inner loop and comparisons are exact fp32.
    run_all(s, std::make_index_sequence<256>{});

    // Cross-group resolution: score = u^2 / (8 + 8k). Empty groups carry
    // gmax = -1 -> sc < 0, never beats a real group (u >= 0 -> sc >= 0).
    float bestSc = -1e30f, bestU = 0.f, bestNorm = 8.f;
    int bestP = 0;
#pragma unroll
    for (int k = 0; k < 9; ++k) {
        float norm = 8.f + 8.f * (float)k;
        float sc = s.gmax[k] * fabsf(s.gmax[k]) * (1.f / (8.f + 8.f * (float)k));
        if (sc > bestSc) {
            bestSc = sc;
            bestU = s.gmax[k];
            bestP = s.gidx[k];
            bestNorm = norm;
        }
    }

    // Least-squares scale for the winning codeword (division, like reference)
    float scale = bestU / bestNorm;
    float s3 = 3.f * scale;

    float o[8];
#pragma unroll
    for (int i = 0; i < 8; ++i) {
        float m = ((bestP >> i) & 1) ? s3 : scale;
        // sign(w)=0 at w==+-0 -> deq 0 in the reference
        float deq = (wv[i] == 0.f) ? 0.f : copysignf(m, wv[i]);
        // STE as computed by the reference: w + (deq - w), same rounding order
        o[i] = wv[i] + (deq - wv[i]);
    }

    float4 r0 = {o[0], o[1], o[2], o[3]};
    float4 r1 = {o[4], o[5], o[6], o[7]};
    float4* out4 = reinterpret_cast<float4*>(out) + 2 * (size_t)b;
    out4[0] = r0;
    out4[1] = r1;
}

extern "C" void kernel_launch(void* const* d_in, const int* in_sizes, int n_in,
                              void* d_out, int out_size) {
    const float* w = (const float*)d_in[0];
    float* out = (float*)d_out;
    int n = in_sizes[0];
    int nb = n / 8;
    int threads = 256;
    int blocks = (nb + threads - 1) / threads;
    iq2xs_kernel<<<blocks, threads>>>(w, out, nb);
}